// round 6
// baseline (speedup 1.0000x reference)
#include <cuda_runtime.h>
#include <cuda_bf16.h>

// Fast Walsh-Hadamard transform, N = 4096, fp32, Sylvester (unnormalized) ordering.
// FWHT_4096 = F16(bits 0-3) (x) F16(bits 4-7) (x) F16(bits 8-11); the three
// radix-16 factors commute, so we apply low bits -> mid bits -> high bits.
// One CTA per row, 256 threads, 16 elements per thread, two smem exchanges
// with XOR swizzle + 272-float pitch for conflict-free LDS/STS.

#define FWHT_N      4096
#define NPAD        272          // 16 blocks of 256 + 16 pad; 272 % 32 == 16

__device__ __forceinline__ void fwht16(float v[16]) {
#pragma unroll
    for (int h = 1; h < 16; h <<= 1) {
#pragma unroll
        for (int i = 0; i < 16; i++) {
            if ((i & h) == 0) {
                float a = v[i];
                float b = v[i + h];
                v[i]     = a + b;
                v[i + h] = a - b;
            }
        }
    }
}

__global__ __launch_bounds__(256, 6)
void HadamardTransform_68891275428167_kernel(const float* __restrict__ x,
                                             float* __restrict__ y) {
    __shared__ float s[16 * NPAD];   // 17408 B

    const int t = threadIdx.x;                 // 0..255
    const size_t row_off = (size_t)blockIdx.x * FWHT_N;
    const float* __restrict__ xr = x + row_off;
    float* __restrict__ yr = y + row_off;

    float v[16];

    // ---- Pass 1: thread t = (c,m) owns all 16 values of l (bits 0-3). ----
    // Load 16 consecutive floats per thread as 4x float4 (warp covers 2KB).
    {
        const float4* __restrict__ xv =
            reinterpret_cast<const float4*>(xr + t * 16);
#pragma unroll
        for (int j = 0; j < 4; j++) {
            float4 f = xv[j];
            v[4 * j + 0] = f.x;
            v[4 * j + 1] = f.y;
            v[4 * j + 2] = f.z;
            v[4 * j + 3] = f.w;
        }
    }
    fwht16(v);   // transform over l

    // ---- Exchange 1: layout s[c*NPAD + m*16 + (l ^ m)] ----
    {
        const int c = t >> 4;
        const int m = t & 15;
        float* base = s + c * NPAD + m * 16;
#pragma unroll
        for (int l = 0; l < 16; l++)
            base[l ^ m] = v[l];
    }
    __syncthreads();
    {
        const int c = t >> 4;
        const int l = t & 15;
        const float* base = s + c * NPAD;
#pragma unroll
        for (int m = 0; m < 16; m++)
            v[m] = base[m * 16 + (l ^ m)];
    }
    fwht16(v);   // transform over m (bits 4-7)

    __syncthreads();   // all reads of exchange-1 done before overwriting

    // ---- Exchange 2: layout s[c*NPAD + m*16 + (l ^ c)] ----
    {
        const int c = t >> 4;
        const int l = t & 15;
        float* base = s + c * NPAD + (l ^ c);
#pragma unroll
        for (int m = 0; m < 16; m++)
            base[m * 16] = v[m];
    }
    __syncthreads();
    {
        const int m = t >> 4;
        const int l = t & 15;
#pragma unroll
        for (int k = 0; k < 16; k++)
            v[k] = s[k * NPAD + m * 16 + (l ^ k)];
    }
    fwht16(v);   // transform over c (bits 8-11)

    // ---- Coalesced store: thread t writes y[k*256 + t], k = 0..15 ----
#pragma unroll
    for (int k = 0; k < 16; k++)
        yr[k * 256 + t] = v[k];
}

extern "C" void kernel_launch(void* const* d_in, const int* in_sizes, int n_in,
                              void* d_out, int out_size) {
    const float* x = (const float*)d_in[0];
    float* y = (float*)d_out;

    const int rows = in_sizes[0] / FWHT_N;   // 16384
    HadamardTransform_68891275428167_kernel<<<rows, 256>>>(x, y);
}